// round 1
// baseline (speedup 1.0000x reference)
#include <cuda_runtime.h>
#include <cuda_bf16.h>
#include <math.h>

// Problem constants
#define NIMG   512        // B*C
#define NALL   1024       // pred + gt images
#define HH     256
#define MM     32
#define NMODE  1024       // 32*32

// Output offsets (tuple order, flattened)
#define OFF_E    0
#define OFF_U    524288
#define OFF_F    1048576
#define OFF_W    1572864
#define OFF_US   2097152
#define OFF_ES   2098176
#define OFF_ERR  2099200
#define OFF_CAL  2623488

// Scratch (no runtime allocation allowed)
__device__ float g_T[(size_t)NALL * 256 * 64];      // per image: [row 0..255][Tc 0..31 | Ts 0..31]
__device__ float g_modes[(size_t)NALL * 2048];      // per image: [re 0..1023 | im 0..1023]
__device__ float g_te[NIMG];                        // total modal energy per (b,c)

// ---------------------------------------------------------------------------
// K1: stage A.  One CTA = one image-half (128 rows).  Folded DFT over n2:
//   Tc[r,k] = x[r,0] + (-1)^k x[r,128] + sum_{n=1..127} (x[r,n]+x[r,256-n]) cos(2pi n k/256)
//   Ts[r,k] =                            sum_{n=1..127} (x[r,n]-x[r,256-n]) sin(2pi n k/256)
// ---------------------------------------------------------------------------
// smem floats: sU[128*129], sV[128*129], sC[128*32], sS[128*32], sX128[128]
#define K1_U  0
#define K1_V  16512
#define K1_C  33024
#define K1_S  37120
#define K1_X  41216
#define K1_SMEM_FLOATS 41344

__global__ __launch_bounds__(256) void k_stageA(const float* __restrict__ pred,
                                                const float* __restrict__ gt)
{
    extern __shared__ float sm[];
    float* sU = sm + K1_U;
    float* sV = sm + K1_V;
    float* sC = sm + K1_C;
    float* sS = sm + K1_S;
    float* sX = sm + K1_X;

    const int img  = blockIdx.x >> 1;
    const int half = blockIdx.x & 1;
    const float* src = (img < NIMG ? pred + (size_t)img * 65536
                                   : gt   + (size_t)(img - NIMG) * 65536)
                       + half * 128 * 256;
    const int tid = threadIdx.x;

    // twiddle tables: sC[n*32+k] = cos(2pi n k/256), sS = sin, n in 0..127
    for (int i = tid; i < 128 * 32; i += 256) {
        int n = i >> 5, k = i & 31;
        int m = (n * k) & 255;                      // period 256 in n*k
        float x = (float)m * (1.0f / 128.0f);       // cos(pi * x)
        sC[i] = cospif(x);
        sS[i] = sinpif(x);
    }
    // fold phase
    for (int i = tid; i < 128 * 128; i += 256) {
        int r = i >> 7, n = i & 127;
        const float* row = src + r * 256;
        float x1 = row[n];
        if (n == 0) { sU[r * 129] = x1; sV[r * 129] = 0.f; }
        else {
            float x2 = row[256 - n];
            sU[r * 129 + n] = x1 + x2;
            sV[r * 129 + n] = x1 - x2;
        }
    }
    if (tid < 128) sX[tid] = src[tid * 256 + 128];
    __syncthreads();

    const int h = tid >> 7;        // 0: cos half, 1: sin half
    const int r = tid & 127;
    const float* base = (h ? sV : sU) + r * 129;
    const float* tab  = h ? sS : sC;

    float acc[32];
#pragma unroll
    for (int k = 0; k < 32; k++) acc[k] = 0.f;

    for (int n = 0; n < 128; n++) {
        float a = base[n];
        const float* t = tab + n * 32;
#pragma unroll
        for (int k = 0; k < 32; k++) acc[k] = fmaf(a, t[k], acc[k]);
    }
    if (h == 0) {
        float x128 = sX[r];
#pragma unroll
        for (int k = 0; k < 32; k++) acc[k] += (k & 1) ? -x128 : x128;
    }
    float* dst = g_T + (size_t)img * 16384 + (size_t)(half * 128 + r) * 64 + h * 32;
#pragma unroll
    for (int q = 0; q < 8; q++)
        ((float4*)dst)[q] = make_float4(acc[q*4], acc[q*4+1], acc[q*4+2], acc[q*4+3]);
}

// ---------------------------------------------------------------------------
// K2: stage B.  One CTA = one image.  modes[k1,k2]:
//   re = sum_n1  c*Tc - s*Ts ;  im = -(sum_n1 c*Ts + s*Tc),  c/s = cos/sin(2pi k1 n1/256)
// ---------------------------------------------------------------------------
// smem floats: sTc[256*32], sTs[256*32], sC2[32*257], sS2[32*257]
#define K2_TC 0
#define K2_TS 8192
#define K2_C  16384
#define K2_S  (16384 + 8224)
#define K2_SMEM_FLOATS (16384 + 8224 + 8224)

__global__ __launch_bounds__(256) void k_stageB()
{
    extern __shared__ float sm[];
    float* sTc = sm + K2_TC;
    float* sTs = sm + K2_TS;
    float* sC  = sm + K2_C;
    float* sS  = sm + K2_S;

    const int img = blockIdx.x;
    const int tid = threadIdx.x;

    const float4* src4 = (const float4*)(g_T + (size_t)img * 16384);
    for (int f = tid; f < 4096; f += 256) {
        int row = f >> 4, q = f & 15;
        float4 v = src4[f];
        if (q < 8) ((float4*)(sTc + row * 32))[q] = v;
        else       ((float4*)(sTs + row * 32))[q - 8] = v;
    }
    for (int i = tid; i < 32 * 256; i += 256) {
        int k1 = i >> 8, n = i & 255;
        int m = (k1 * n) & 255;
        float x = (float)m * (1.0f / 128.0f);
        sC[k1 * 257 + n] = cospif(x);
        sS[k1 * 257 + n] = sinpif(x);
    }
    __syncthreads();

    const int k1 = tid >> 3;
    const int g  = tid & 7;
    const float* cp = sC + k1 * 257;
    const float* sp = sS + k1 * 257;

    float re[4] = {0,0,0,0}, im[4] = {0,0,0,0};
    for (int n = 0; n < 256; n++) {
        float c = cp[n], s = sp[n];
        float4 tc4 = *(const float4*)(sTc + n * 32 + g * 4);
        float4 ts4 = *(const float4*)(sTs + n * 32 + g * 4);
        float tc[4] = {tc4.x, tc4.y, tc4.z, tc4.w};
        float ts[4] = {ts4.x, ts4.y, ts4.z, ts4.w};
#pragma unroll
        for (int j = 0; j < 4; j++) {
            re[j] = fmaf(c, tc[j], re[j]);
            re[j] = fmaf(-s, ts[j], re[j]);
            im[j] = fmaf(c, ts[j], im[j]);
            im[j] = fmaf(s, tc[j], im[j]);
        }
    }
    float* mre = g_modes + (size_t)img * 2048 + k1 * 32 + g * 4;
    float* mim = mre + 1024;
    *(float4*)mre = make_float4(re[0], re[1], re[2], re[3]);
    *(float4*)mim = make_float4(-im[0], -im[1], -im[2], -im[3]);
}

// ---------------------------------------------------------------------------
// K3: fused energies / errors / MLP uncertainty.  One thread = one pred mode.
// h1 is never materialized: fused into the 64-iteration accumulation of h2.
// ---------------------------------------------------------------------------
__global__ __launch_bounds__(256) void k_mlp(const float* __restrict__ W1,
                                             const float* __restrict__ b1,
                                             const float* __restrict__ W2,
                                             const float* __restrict__ b2,
                                             const float* __restrict__ W3,
                                             const float* __restrict__ b3,
                                             float* __restrict__ out)
{
    __shared__ float sW1[128], sb1[64], sW2[2048], sb2[32], sW3[32], sb3;
    const int tid = threadIdx.x;
    for (int i = tid; i < 128;  i += 256) sW1[i] = W1[i];
    for (int i = tid; i < 2048; i += 256) sW2[i] = W2[i];
    if (tid < 64) sb1[tid] = b1[tid];
    if (tid < 32) { sb2[tid] = b2[tid]; sW3[tid] = W3[tid]; }
    if (tid == 0) sb3 = b3[0];
    __syncthreads();

    const int m    = blockIdx.x * 256 + tid;       // 0..524287
    const int img  = m >> 10;
    const int mode = m & 1023;

    const float pr = g_modes[(size_t)img * 2048 + mode];
    const float pi = g_modes[(size_t)img * 2048 + 1024 + mode];
    const float gr = g_modes[(size_t)(NIMG + img) * 2048 + mode];
    const float gi = g_modes[(size_t)(NIMG + img) * 2048 + 1024 + mode];

    out[OFF_E + m] = fmaf(pr, pr, pi * pi);
    float dr = pr - gr, di = pi - gi;
    out[OFF_ERR + m] = fmaf(dr, dr, di * di);

    float h2[32];
#pragma unroll
    for (int j = 0; j < 32; j++) h2[j] = sb2[j];

    for (int i = 0; i < 64; i++) {
        float a = fmaf(pr, sW1[i], fmaf(pi, sW1[64 + i], sb1[i]));
        a = a > 0.f ? a : 0.f;                      // ReLU(h1[i])
        const float* w = sW2 + i * 32;
#pragma unroll
        for (int j = 0; j < 32; j++) h2[j] = fmaf(a, w[j], h2[j]);
    }
    float o = sb3;
#pragma unroll
    for (int j = 0; j < 32; j++) {
        float v = h2[j] > 0.f ? h2[j] : 0.f;
        o = fmaf(v, sW3[j], o);
    }
    // softplus
    out[OFF_U + m] = fmaxf(o, 0.f) + log1pf(expf(-fabsf(o)));
}

// ---------------------------------------------------------------------------
// K4a: total modal energy per (b,c)
// ---------------------------------------------------------------------------
__global__ __launch_bounds__(256) void k_totalE(const float* __restrict__ out)
{
    __shared__ float red[256];
    const int img = blockIdx.x;
    const int tid = threadIdx.x;
    float s = 0.f;
    for (int i = tid; i < 1024; i += 256) s += out[(size_t)img * 1024 + i];
    red[tid] = s;
    __syncthreads();
    for (int w = 128; w > 0; w >>= 1) {
        if (tid < w) red[tid] += red[tid + w];
        __syncthreads();
    }
    if (tid == 0) g_te[img] = red[0];
}

// ---------------------------------------------------------------------------
// K4b: energy fractions + weighted importance (elementwise)
// ---------------------------------------------------------------------------
__global__ __launch_bounds__(256) void k_frac(float* __restrict__ out)
{
    const int m = blockIdx.x * 256 + threadIdx.x;
    const int img = m >> 10;
    float e = out[OFF_E + m];
    float f = e / (g_te[img] + 1e-8f);
    out[OFF_F + m] = f;
    out[OFF_W + m] = f * out[OFF_U + m];
}

// ---------------------------------------------------------------------------
// K4c: per-mode statistics over the 512 samples: spectra means + Pearson corr.
// ---------------------------------------------------------------------------
__global__ __launch_bounds__(256) void k_stats(float* __restrict__ out)
{
    const int k = blockIdx.x * 256 + threadIdx.x;   // 0..1023
    double su = 0, se = 0, sue = 0, suu = 0, see = 0, sen = 0;
    for (int s = 0; s < NIMG; s++) {
        float u  = out[OFF_U   + (size_t)s * 1024 + k];
        float e  = out[OFF_ERR + (size_t)s * 1024 + k];
        float en = out[OFF_E   + (size_t)s * 1024 + k];
        su  += u;  se += e;  sen += en;
        sue += (double)u * (double)e;
        suu += (double)u * (double)u;
        see += (double)e * (double)e;
    }
    out[OFF_US + k] = (float)(su  * (1.0 / 512.0));
    out[OFF_ES + k] = (float)(sen * (1.0 / 512.0));
    double num  = sue - su * se * (1.0 / 512.0);
    double varu = suu - su * su * (1.0 / 512.0);
    double vare = see - se * se * (1.0 / 512.0);
    out[OFF_CAL + k] = (float)(num / (sqrt(varu * vare) + 1e-8));
}

// ---------------------------------------------------------------------------
extern "C" void kernel_launch(void* const* d_in, const int* in_sizes, int n_in,
                              void* d_out, int out_size)
{
    const float* pred = (const float*)d_in[0];
    // d_in[1] = uncertainty: unused by the reference
    const float* gt   = (const float*)d_in[2];
    const float* W1   = (const float*)d_in[3];
    const float* b1   = (const float*)d_in[4];
    const float* W2   = (const float*)d_in[5];
    const float* b2   = (const float*)d_in[6];
    const float* W3   = (const float*)d_in[7];
    const float* b3   = (const float*)d_in[8];
    float* out = (float*)d_out;

    const int smemA = K1_SMEM_FLOATS * 4;   // 165376 B
    const int smemB = K2_SMEM_FLOATS * 4;   // 131328 B
    cudaFuncSetAttribute(k_stageA, cudaFuncAttributeMaxDynamicSharedMemorySize, smemA);
    cudaFuncSetAttribute(k_stageB, cudaFuncAttributeMaxDynamicSharedMemorySize, smemB);

    k_stageA<<<2048, 256, smemA>>>(pred, gt);
    k_stageB<<<1024, 256, smemB>>>();
    k_mlp<<<2048, 256>>>(W1, b1, W2, b2, W3, b3, out);
    k_totalE<<<512, 256>>>(out);
    k_frac<<<2048, 256>>>(out);
    k_stats<<<4, 256>>>(out);
}

// round 4
// speedup vs baseline: 1.7664x; 1.7664x over previous
#include <cuda_runtime.h>
#include <cuda_bf16.h>
#include <math.h>

// Problem constants
#define NIMG   512        // B*C
#define NALL   1024       // pred + gt images

// Output offsets (tuple order, flattened)
#define OFF_E    0
#define OFF_U    524288
#define OFF_F    1048576
#define OFF_W    1572864
#define OFF_US   2097152
#define OFF_ES   2098176
#define OFF_ERR  2099200
#define OFF_CAL  2623488

// ---------------------------------------------------------------------------
// Compile-time twiddle table: cos/sin(2*pi*m/256) as float literals so the
// fully-unrolled DFT loops become FFMA-with-immediate (rt_SMSP=1 on sm_10x).
// __device__ constexpr: visible in device code WITHOUT --expt-relaxed-constexpr;
// constant-global loads with constant indices fold to immediates in NVVM.
// ---------------------------------------------------------------------------
struct Tw { float c[256]; float s[256]; };

__host__ __device__ constexpr double k_cpi_taylor(double x) {  // cos(x)
    double term = 1.0, sum = 1.0, x2 = x * x;
    for (int j = 1; j <= 14; j++) { term *= -x2 / double((2*j-1)*(2*j)); sum += term; }
    return sum;
}
__host__ __device__ constexpr double k_cos256(int m) {         // cos(2*pi*m/256)
    m &= 255;
    if (m > 128) m = 256 - m;
    constexpr double PI = 3.14159265358979323846;
    if (m <= 64) return  k_cpi_taylor(PI * (double)m / 128.0);
    return -k_cpi_taylor(PI * (double)(128 - m) / 128.0);
}
__host__ __device__ constexpr Tw k_mktw() {
    Tw t{};
    for (int m = 0; m < 256; m++) {
        t.c[m] = (float)k_cos256(m);
        t.s[m] = (float)k_cos256(m + 192);   // sin(th) = cos(th - pi/2)
    }
    return t;
}
__device__ constexpr Tw TW = k_mktw();

// ---------------------------------------------------------------------------
// Scratch.  g_T2 layout: [img][c 0..63][row 0..255]; c<32: Tc(k2=c), else Ts.
// ---------------------------------------------------------------------------
__device__ float g_T2[(size_t)NALL * 64 * 256];
__device__ float g_modes[(size_t)NALL * 2048];      // [re 0..1023 | im 0..1023]
__device__ float g_te[NIMG];

// smem layout (floats): four folded arrays, each [n 0..63][64 + pad]
#define A0 0
#define A1 4176
#define A2 8352
#define A3 12528
#define SMEM_FLOATS 16704        // 66816 B -> 3 CTAs/SM

// ---------------------------------------------------------------------------
// K1: stage A (row rfft, double-folded).  CTA = 64 rows (quarter image),
// 128 threads: warp w -> parity p=(w&1), rows (w>>1)*32 + lane.
//   Tc[k] = x0 + (-1)^k x128 + [k even: u64*(-1)^(k/2)]
//           + sum_{n=1..63} (u[n] +- u[128-n]) cos(2pi n k/256)
//   Ts[k] = [k odd: v64*(-1)^((k-1)/2)] + sum (v[n] -+ v[128-n]) sin(...)
// with u[n]=x[n]+x[256-n], v[n]=x[n]-x[256-n].
// ---------------------------------------------------------------------------
__global__ __launch_bounds__(128) void k_stageA(const float* __restrict__ pred,
                                                const float* __restrict__ gt)
{
    extern __shared__ float sm[];
    float* sCE = sm + A0;   // even-k cos source; n=0 slot: x[0]
    float* sCO = sm + A1;   // odd-k  cos source; n=0 slot: x[128]
    float* sSE = sm + A2;   // even-k sin source; n=0 slot: u64
    float* sSO = sm + A3;   // odd-k  sin source; n=0 slot: v64

    const int img = blockIdx.x >> 2;
    const int q   = blockIdx.x & 3;
    const float* src = (img < NIMG ? pred + (size_t)img * 65536
                                   : gt   + (size_t)(img - NIMG) * 65536)
                       + q * 64 * 256;
    const int tid = threadIdx.x;

    // Fold: lanes sweep n (coalesced LDG), stride-65 STS (conflict-free).
    for (int i = tid; i < 4096; i += 128) {
        int r = i >> 6, n = i & 63;
        const float* row = src + r * 256;
        if (n == 0) {
            sCE[r] = row[0];
            sCO[r] = row[128];
            float a = row[64], b = row[192];
            sSE[r] = a + b;
            sSO[r] = a - b;
        } else {
            float a = row[n], b = row[256 - n], c = row[128 - n], d = row[128 + n];
            float u1 = a + b, u2 = c + d, v1 = a - b, v2 = c - d;
            sCE[n * 65 + r] = u1 + u2;
            sCO[n * 65 + r] = u1 - u2;
            sSE[n * 65 + r] = v1 - v2;
            sSO[n * 65 + r] = v1 + v2;
        }
    }
    __syncthreads();

    const int r = (tid & 31) | ((tid >> 6) << 5);   // 0..63
    const int p = (tid >> 5) & 1;                   // warp-uniform parity

    float ac[16], as[16];
#pragma unroll
    for (int j = 0; j < 16; j++) { ac[j] = 0.f; as[j] = 0.f; }

    if (p == 0) {
#pragma unroll
        for (int n = 1; n < 64; n++) {
            float cu = sCE[n * 65 + r];
            float sv = sSE[n * 65 + r];
#pragma unroll
            for (int j = 0; j < 16; j++) {
                ac[j] = fmaf(cu, TW.c[(n * 2 * j) & 255], ac[j]);
                if (j) as[j] = fmaf(sv, TW.s[(n * 2 * j) & 255], as[j]);
            }
        }
        float x0 = sCE[r], x128 = sCO[r], u64v = sSE[r];
#pragma unroll
        for (int j = 0; j < 16; j++)
            ac[j] += x0 + x128 + ((j & 1) ? -u64v : u64v);
    } else {
#pragma unroll
        for (int n = 1; n < 64; n++) {
            float cu = sCO[n * 65 + r];
            float sv = sSO[n * 65 + r];
#pragma unroll
            for (int j = 0; j < 16; j++) {
                ac[j] = fmaf(cu, TW.c[(n * (2 * j + 1)) & 255], ac[j]);
                as[j] = fmaf(sv, TW.s[(n * (2 * j + 1)) & 255], as[j]);
            }
        }
        float x0 = sCE[r], x128 = sCO[r], v64v = sSO[r];
#pragma unroll
        for (int j = 0; j < 16; j++) {
            ac[j] += x0 - x128;
            as[j] += (j & 1) ? -v64v : v64v;
        }
    }

    // Coalesced STG: lanes span 32 consecutive rows per k.
    float* dst = g_T2 + (size_t)img * 16384 + q * 64 + r;
#pragma unroll
    for (int j = 0; j < 16; j++) {
        int k = 2 * j + p;
        dst[k * 256]        = ac[j];
        dst[(32 + k) * 256] = as[j];
    }
}

// ---------------------------------------------------------------------------
// K2: stage B (column DFT over rows, double-folded).  CTA = 1 image,
// 128 threads: warp parity split as in K1, columns c = 0..63.
//   A_c[k] = sum_n col[n] cos(2pi n k/256),  B_c[k] = sum_n col[n] sin(...)
//   re[k1][k2] = A_{Tc k2}[k1] - B_{Ts k2}[k1]
//   im[k1][k2] = -(B_{Tc k2}[k1] + A_{Ts k2}[k1])
// ---------------------------------------------------------------------------
__global__ __launch_bounds__(128) void k_stageB()
{
    extern __shared__ float sm[];
    float* sX1 = sm + A0;   // cos even; n=0: col[0]
    float* sX2 = sm + A1;   // cos odd ; n=0: col[128]
    float* sX3 = sm + A2;   // sin even; n=0: col[64]+col[192]
    float* sX4 = sm + A3;   // sin odd ; n=0: col[64]-col[192]
    float* sRA = sm;                // reuse after compute: A[c][k], stride 67
    float* sRB = sm + 4288;         // B[c][k]

    const int img = blockIdx.x;
    const int tid = threadIdx.x;
    const float* base = g_T2 + (size_t)img * 16384;

    for (int i = tid; i < 4096; i += 128) {
        int c = i >> 6, n = i & 63;
        const float* col = base + c * 256;
        if (n == 0) {
            sX1[c] = col[0];
            sX2[c] = col[128];
            float a = col[64], b = col[192];
            sX3[c] = a + b;
            sX4[c] = a - b;
        } else {
            float a = col[n], b = col[256 - n], e = col[128 - n], d = col[128 + n];
            float p1 = a + b, p2 = e + d, q1 = a - b, q2 = e - d;
            sX1[n * 65 + c] = p1 + p2;
            sX2[n * 65 + c] = p1 - p2;
            sX3[n * 65 + c] = q1 - q2;
            sX4[n * 65 + c] = q1 + q2;
        }
    }
    __syncthreads();

    const int c = (tid & 31) | ((tid >> 6) << 5);
    const int p = (tid >> 5) & 1;

    float aA[16], aB[16];
#pragma unroll
    for (int j = 0; j < 16; j++) { aA[j] = 0.f; aB[j] = 0.f; }

    if (p == 0) {
#pragma unroll
        for (int n = 1; n < 64; n++) {
            float cu = sX1[n * 65 + c];
            float sv = sX3[n * 65 + c];
#pragma unroll
            for (int j = 0; j < 16; j++) {
                aA[j] = fmaf(cu, TW.c[(n * 2 * j) & 255], aA[j]);
                if (j) aB[j] = fmaf(sv, TW.s[(n * 2 * j) & 255], aB[j]);
            }
        }
        float s0 = sX1[c], s128 = sX2[c], pe64 = sX3[c];
#pragma unroll
        for (int j = 0; j < 16; j++)
            aA[j] += s0 + s128 + ((j & 1) ? -pe64 : pe64);
    } else {
#pragma unroll
        for (int n = 1; n < 64; n++) {
            float cu = sX2[n * 65 + c];
            float sv = sX4[n * 65 + c];
#pragma unroll
            for (int j = 0; j < 16; j++) {
                aA[j] = fmaf(cu, TW.c[(n * (2 * j + 1)) & 255], aA[j]);
                aB[j] = fmaf(sv, TW.s[(n * (2 * j + 1)) & 255], aB[j]);
            }
        }
        float s0 = sX1[c], s128 = sX2[c], po64 = sX4[c];
#pragma unroll
        for (int j = 0; j < 16; j++) {
            aA[j] += s0 - s128;
            aB[j] += (j & 1) ? -po64 : po64;
        }
    }
    __syncthreads();   // everyone done reading fold arrays; reuse as sRA/sRB

#pragma unroll
    for (int j = 0; j < 16; j++) {
        int k = 2 * j + p;
        sRA[c * 67 + k] = aA[j];
        sRB[c * 67 + k] = aB[j];
    }
    __syncthreads();

    float* mp = g_modes + (size_t)img * 2048;
    for (int idx = tid; idx < 1024; idx += 128) {
        int k1 = idx >> 5, k2 = idx & 31;
        float ATc = sRA[k2 * 67 + k1];
        float BTs = sRB[(32 + k2) * 67 + k1];
        float BTc = sRB[k2 * 67 + k1];
        float ATs = sRA[(32 + k2) * 67 + k1];
        mp[idx]        = ATc - BTs;
        mp[1024 + idx] = -(BTc + ATs);
    }
}

// ---------------------------------------------------------------------------
// K3: fused energies / errors / MLP.  2 modes per thread.
// ---------------------------------------------------------------------------
__global__ __launch_bounds__(256) void k_mlp(const float* __restrict__ W1,
                                             const float* __restrict__ b1,
                                             const float* __restrict__ W2,
                                             const float* __restrict__ b2,
                                             const float* __restrict__ W3,
                                             const float* __restrict__ b3,
                                             float* __restrict__ out)
{
    __shared__ float sW1[128], sb1[64], sW2[2048], sb2[32], sW3[32], sb3;
    const int tid = threadIdx.x;
    for (int i = tid; i < 128;  i += 256) sW1[i] = W1[i];
    for (int i = tid; i < 2048; i += 256) sW2[i] = W2[i];
    if (tid < 64) sb1[tid] = b1[tid];
    if (tid < 32) { sb2[tid] = b2[tid]; sW3[tid] = W3[tid]; }
    if (tid == 0) sb3 = b3[0];
    __syncthreads();

    const int m0   = (blockIdx.x * 256 + tid) * 2;
    const int img  = m0 >> 10;
    const int mode = m0 & 1023;

    const float* mp = g_modes + (size_t)img * 2048 + mode;
    const float* mg = g_modes + (size_t)(NIMG + img) * 2048 + mode;
    float2 pr = *(const float2*)mp;
    float2 pi = *(const float2*)(mp + 1024);
    float2 gr = *(const float2*)mg;
    float2 gi = *(const float2*)(mg + 1024);

    *(float2*)&out[OFF_E + m0] =
        make_float2(fmaf(pr.x, pr.x, pi.x * pi.x), fmaf(pr.y, pr.y, pi.y * pi.y));
    float drx = pr.x - gr.x, dix = pi.x - gi.x;
    float dry = pr.y - gr.y, diy = pi.y - gi.y;
    *(float2*)&out[OFF_ERR + m0] =
        make_float2(fmaf(drx, drx, dix * dix), fmaf(dry, dry, diy * diy));

    float h2a[32], h2b[32];
#pragma unroll
    for (int j = 0; j < 32; j++) { h2a[j] = sb2[j]; h2b[j] = sb2[j]; }

#pragma unroll 8
    for (int i = 0; i < 64; i++) {
        float w1a = sW1[i], w1b = sW1[64 + i], bb = sb1[i];
        float a0 = fmaf(pr.x, w1a, fmaf(pi.x, w1b, bb));
        float a1 = fmaf(pr.y, w1a, fmaf(pi.y, w1b, bb));
        a0 = a0 > 0.f ? a0 : 0.f;
        a1 = a1 > 0.f ? a1 : 0.f;
        const float4* w4 = (const float4*)(sW2 + i * 32);
#pragma unroll
        for (int q = 0; q < 8; q++) {
            float4 w = w4[q];
            h2a[q*4+0] = fmaf(a0, w.x, h2a[q*4+0]);
            h2a[q*4+1] = fmaf(a0, w.y, h2a[q*4+1]);
            h2a[q*4+2] = fmaf(a0, w.z, h2a[q*4+2]);
            h2a[q*4+3] = fmaf(a0, w.w, h2a[q*4+3]);
            h2b[q*4+0] = fmaf(a1, w.x, h2b[q*4+0]);
            h2b[q*4+1] = fmaf(a1, w.y, h2b[q*4+1]);
            h2b[q*4+2] = fmaf(a1, w.z, h2b[q*4+2]);
            h2b[q*4+3] = fmaf(a1, w.w, h2b[q*4+3]);
        }
    }
    float o0 = sb3, o1 = sb3;
#pragma unroll
    for (int j = 0; j < 32; j++) {
        float va = h2a[j] > 0.f ? h2a[j] : 0.f;
        float vb = h2b[j] > 0.f ? h2b[j] : 0.f;
        o0 = fmaf(va, sW3[j], o0);
        o1 = fmaf(vb, sW3[j], o1);
    }
    *(float2*)&out[OFF_U + m0] =
        make_float2(fmaxf(o0, 0.f) + log1pf(expf(-fabsf(o0))),
                    fmaxf(o1, 0.f) + log1pf(expf(-fabsf(o1))));
}

// ---------------------------------------------------------------------------
// K4a: total modal energy per (b,c)
// ---------------------------------------------------------------------------
__global__ __launch_bounds__(256) void k_totalE(const float* __restrict__ out)
{
    __shared__ float red[256];
    const int img = blockIdx.x;
    const int tid = threadIdx.x;
    float s = 0.f;
    for (int i = tid; i < 1024; i += 256) s += out[OFF_E + (size_t)img * 1024 + i];
    red[tid] = s;
    __syncthreads();
    for (int w = 128; w > 0; w >>= 1) {
        if (tid < w) red[tid] += red[tid + w];
        __syncthreads();
    }
    if (tid == 0) g_te[img] = red[0];
}

// ---------------------------------------------------------------------------
// K4b: energy fractions + weighted importance
// ---------------------------------------------------------------------------
__global__ __launch_bounds__(256) void k_frac(float* __restrict__ out)
{
    const int m = blockIdx.x * 256 + threadIdx.x;
    const int img = m >> 10;
    float e = out[OFF_E + m];
    float f = e / (g_te[img] + 1e-8f);
    out[OFF_F + m] = f;
    out[OFF_W + m] = f * out[OFF_U + m];
}

// ---------------------------------------------------------------------------
// K4c: per-mode stats.  128 CTAs x 256 thr: CTA owns 8 modes, 32 sample
// groups of 16.  fp64 accumulators (Pearson cancellation), smem tree reduce.
// ---------------------------------------------------------------------------
__global__ __launch_bounds__(256) void k_stats(float* __restrict__ out)
{
    __shared__ double red[6][256];
    const int tid = threadIdx.x;
    const int kl  = tid & 7;
    const int sg  = tid >> 3;                 // 0..31
    const int k   = blockIdx.x * 8 + kl;

    double su = 0, se = 0, sen = 0, sue = 0, suu = 0, see = 0;
    for (int s = sg; s < NIMG; s += 32) {
        float u  = out[OFF_U   + (size_t)s * 1024 + k];
        float e  = out[OFF_ERR + (size_t)s * 1024 + k];
        float en = out[OFF_E   + (size_t)s * 1024 + k];
        su += u; se += e; sen += en;
        sue += (double)u * (double)e;
        suu += (double)u * (double)u;
        see += (double)e * (double)e;
    }
    red[0][tid] = su;  red[1][tid] = se;  red[2][tid] = sen;
    red[3][tid] = sue; red[4][tid] = suu; red[5][tid] = see;
    __syncthreads();

    for (int off = 16; off >= 1; off >>= 1) {
        if (sg < off) {
#pragma unroll
            for (int m = 0; m < 6; m++)
                red[m][tid] += red[m][tid + off * 8];
        }
        __syncthreads();
    }
    if (tid < 8) {
        double tsu = red[0][tid], tse = red[1][tid], tsen = red[2][tid];
        double tsue = red[3][tid], tsuu = red[4][tid], tsee = red[5][tid];
        out[OFF_US + k] = (float)(tsu  * (1.0 / 512.0));
        out[OFF_ES + k] = (float)(tsen * (1.0 / 512.0));
        double num  = tsue - tsu * tse * (1.0 / 512.0);
        double varu = tsuu - tsu * tsu * (1.0 / 512.0);
        double vare = tsee - tse * tse * (1.0 / 512.0);
        out[OFF_CAL + k] = (float)(num / (sqrt(varu * vare) + 1e-8));
    }
}

// ---------------------------------------------------------------------------
extern "C" void kernel_launch(void* const* d_in, const int* in_sizes, int n_in,
                              void* d_out, int out_size)
{
    const float* pred = (const float*)d_in[0];
    // d_in[1] = uncertainty: unused by the reference
    const float* gt   = (const float*)d_in[2];
    const float* W1   = (const float*)d_in[3];
    const float* b1   = (const float*)d_in[4];
    const float* W2   = (const float*)d_in[5];
    const float* b2   = (const float*)d_in[6];
    const float* W3   = (const float*)d_in[7];
    const float* b3   = (const float*)d_in[8];
    float* out = (float*)d_out;

    const int smem = SMEM_FLOATS * 4;   // 66816 B
    cudaFuncSetAttribute(k_stageA, cudaFuncAttributeMaxDynamicSharedMemorySize, smem);
    cudaFuncSetAttribute(k_stageB, cudaFuncAttributeMaxDynamicSharedMemorySize, smem);

    k_stageA<<<4096, 128, smem>>>(pred, gt);
    k_stageB<<<1024, 128, smem>>>();
    k_mlp<<<1024, 256>>>(W1, b1, W2, b2, W3, b3, out);
    k_totalE<<<512, 256>>>(out);
    k_frac<<<2048, 256>>>(out);
    k_stats<<<128, 256>>>(out);
}